// round 1
// baseline (speedup 1.0000x reference)
#include <cuda_runtime.h>
#include <math.h>

#define TT 512
#define BB 32
#define DD 1024
#define NBLK 128       // scan grid size (<= 148 SMs -> all resident, barrier is safe)
#define EPB 8          // e-rows of W_h per scan block

// ---------------- scratch (static device memory; no allocations) ----------------
__device__ float    g_Wx[(size_t)TT * BB * DD];   // 64 MB: precomputed x@W_x^T + b
__device__ float    g_hT[2][DD * BB];             // double-buffered h, transposed [d][b]
__device__ unsigned g_cnt[TT];                    // per-step arrival counters

// ---------------- init: reset counters, load h0 (transposed) ----------------
__global__ void init_kernel(const float* __restrict__ h0) {
    int idx = blockIdx.x * blockDim.x + threadIdx.x;   // 0..32767
    if (idx < TT) g_cnt[idx] = 0u;
    if (idx < DD * BB) {
        int d = idx >> 5;
        int b = idx & 31;
        g_hT[0][idx] = h0[b * DD + d];   // idx == d*32 + b
    }
}

// ---------------- phase 1: Wx[m][e] = sum_k x[m][k] * W_x[e][k] + bias[e] ----------------
// M = T*B = 16384, N = 1024, K = 1024. Both operands K-major (NT gemm).
__global__ void __launch_bounds__(256) gemm_wx_kernel(
    const float* __restrict__ x,
    const float* __restrict__ Wxw,
    const float* __restrict__ bias)
{
    __shared__ float As[16][128];
    __shared__ float Bs[16][128];

    const int tid = threadIdx.x;
    const int tx = tid & 15;
    const int ty = tid >> 4;
    const int m0 = blockIdx.y * 128;
    const int n0 = blockIdx.x * 128;

    float acc[8][8] = {};

    for (int kt = 0; kt < DD; kt += 16) {
        // stage A and B tiles (transposed into [k][row] layout)
        #pragma unroll
        for (int u = 0; u < 2; u++) {
            int fi = tid + u * 256;       // float4 index 0..511
            int r  = fi >> 2;             // row 0..127
            int c  = fi & 3;              // which float4 in the 16-wide k strip
            float4 va = *(const float4*)&x[(size_t)(m0 + r) * DD + kt + c * 4];
            As[c * 4 + 0][r] = va.x; As[c * 4 + 1][r] = va.y;
            As[c * 4 + 2][r] = va.z; As[c * 4 + 3][r] = va.w;
            float4 vb = *(const float4*)&Wxw[(size_t)(n0 + r) * DD + kt + c * 4];
            Bs[c * 4 + 0][r] = vb.x; Bs[c * 4 + 1][r] = vb.y;
            Bs[c * 4 + 2][r] = vb.z; Bs[c * 4 + 3][r] = vb.w;
        }
        __syncthreads();

        #pragma unroll
        for (int k = 0; k < 16; k++) {
            float4 a0 = *(const float4*)&As[k][ty * 8];
            float4 a1 = *(const float4*)&As[k][ty * 8 + 4];
            float4 b0 = *(const float4*)&Bs[k][tx * 8];
            float4 b1 = *(const float4*)&Bs[k][tx * 8 + 4];
            float a[8] = {a0.x, a0.y, a0.z, a0.w, a1.x, a1.y, a1.z, a1.w};
            float b[8] = {b0.x, b0.y, b0.z, b0.w, b1.x, b1.y, b1.z, b1.w};
            #pragma unroll
            for (int i = 0; i < 8; i++)
                #pragma unroll
                for (int j = 0; j < 8; j++)
                    acc[i][j] += a[i] * b[j];
        }
        __syncthreads();
    }

    float4 bi0 = *(const float4*)&bias[n0 + tx * 8];
    float4 bi1 = *(const float4*)&bias[n0 + tx * 8 + 4];
    float bb[8] = {bi0.x, bi0.y, bi0.z, bi0.w, bi1.x, bi1.y, bi1.z, bi1.w};

    #pragma unroll
    for (int i = 0; i < 8; i++) {
        size_t row = (size_t)(m0 + ty * 8 + i) * DD + n0 + tx * 8;
        float4 o0 = make_float4(acc[i][0] + bb[0], acc[i][1] + bb[1],
                                acc[i][2] + bb[2], acc[i][3] + bb[3]);
        float4 o1 = make_float4(acc[i][4] + bb[4], acc[i][5] + bb[5],
                                acc[i][6] + bb[6], acc[i][7] + bb[7]);
        *(float4*)&g_Wx[row]     = o0;
        *(float4*)&g_Wx[row + 4] = o1;
    }
}

// ---------------- phase 2: persistent sequential scan ----------------
// Block bi owns e-rows [bi*8, bi*8+8) of W_h (resident in smem).
// Per step: out[b][e] = tanh( Wx[t][b][e] + sum_d h[d][b] * W_h[e][d] )
// Thread layout: 16 spatial threads (2 e-groups x 8 b-groups, 4x4 register tile)
//                x 16-way d-split (64 d each). Partial sums folded 2:1 by warp
//                shuffle, then 8-way via smem.
__global__ void __launch_bounds__(256) scan_kernel(
    const float* __restrict__ z,
    const float* __restrict__ Wh,
    float* __restrict__ out)
{
    __shared__ float Ws[EPB][DD];     // 32 KB, loaded once
    __shared__ float red[8 * 257];    // 8.2 KB reduction buffer (padded)

    const int tid = threadIdx.x;
    const int e0  = blockIdx.x * EPB;

    // load W_h slice (8 rows x 1024), coalesced float4
    #pragma unroll
    for (int u = 0; u < 8; u++) {
        int fi = tid + u * 256;           // float4 index 0..2047
        int r  = fi >> 8;                 // 0..7
        int c  = (fi & 255) * 4;          // 0..1020
        *(float4*)&Ws[r][c] = *(const float4*)&Wh[(size_t)(e0 + r) * DD + c];
    }
    __syncthreads();

    // producer mapping
    const int ds  = tid >> 4;          // d-slice 0..15
    const int sid = tid & 15;
    const int eg  = sid >> 3;          // 0..1  (4 e's each)
    const int bg  = sid & 7;           // 0..7  (4 b's each)
    const int d_base = ds * 64;

    // consumer mapping: one output per thread
    const int cb  = tid >> 3;          // b 0..31
    const int ce  = tid & 7;           // e_local 0..7
    const int ridx = tid ^ (((tid >> 5) & 7) << 2);   // bank-swizzled slot

    const size_t OUT2 = (size_t)TT * BB * DD;

    for (int t = 0; t < TT; t++) {
        const float* __restrict__ h = g_hT[t & 1];

        // prefetch this thread's Wx and z (independent of h)
        const int m = t * BB + cb;
        const size_t mo = (size_t)m * DD + e0 + ce;
        float wx = g_Wx[mo];
        float zv = z[mo];

        float acc[4][4] = {};
        #pragma unroll 4
        for (int it = 0; it < 16; it++) {
            int d = d_base + it * 4;
            float4 h0v = *(const float4*)&h[(d + 0) * BB + bg * 4];
            float4 h1v = *(const float4*)&h[(d + 1) * BB + bg * 4];
            float4 h2v = *(const float4*)&h[(d + 2) * BB + bg * 4];
            float4 h3v = *(const float4*)&h[(d + 3) * BB + bg * 4];
            #pragma unroll
            for (int i = 0; i < 4; i++) {
                float4 w = *(const float4*)&Ws[eg * 4 + i][d];
                acc[i][0] += w.x * h0v.x + w.y * h1v.x + w.z * h2v.x + w.w * h3v.x;
                acc[i][1] += w.x * h0v.y + w.y * h1v.y + w.z * h2v.y + w.w * h3v.y;
                acc[i][2] += w.x * h0v.z + w.y * h1v.z + w.z * h2v.z + w.w * h3v.z;
                acc[i][3] += w.x * h0v.w + w.y * h1v.w + w.z * h2v.w + w.w * h3v.w;
            }
        }

        // fold adjacent d-slices (lanes l and l+16 share spatial id)
        #pragma unroll
        for (int i = 0; i < 4; i++)
            #pragma unroll
            for (int j = 0; j < 4; j++)
                acc[i][j] += __shfl_down_sync(0xFFFFFFFFu, acc[i][j], 16);

        if ((ds & 1) == 0) {
            int r = ds >> 1;   // 0..7 == warp id
            #pragma unroll
            for (int i = 0; i < 4; i++)
                #pragma unroll
                for (int j = 0; j < 4; j++) {
                    int flat = (bg * 4 + j) * 8 + eg * 4 + i;    // b*8 + e_local
                    int slot = flat ^ (((flat >> 5) & 7) << 2);  // bank swizzle
                    red[r * 257 + slot] = acc[i][j];
                }
        }
        __syncthreads();

        // consume: final 8-way sum + epilogue
        float s = 0.0f;
        #pragma unroll
        for (int r = 0; r < 8; r++) s += red[r * 257 + ridx];

        float pre = s + wx;
        float hn  = tanhf(pre);
        float sig = 1.0f / (1.0f + __expf(-zv));
        float ov  = hn * (zv * sig);

        out[mo]        = hn;   // h_all
        out[OUT2 + mo] = ov;   // outputs
        g_hT[(t + 1) & 1][(e0 + ce) * BB + cb] = hn;   // transposed next-h

        __syncthreads();       // red consumed + h writes done (block-wide)

        // inter-block barrier for step t (single arrival per block, L2 spin)
        if (tid == 0) {
            __threadfence();
            atomicAdd(&g_cnt[t], 1u);
            volatile unsigned* p = &g_cnt[t];
            while (*p < (unsigned)NBLK) { }
            __threadfence();
        }
        __syncthreads();
    }
}

// ---------------- launch ----------------
extern "C" void kernel_launch(void* const* d_in, const int* in_sizes, int n_in,
                              void* d_out, int out_size) {
    const float* x    = (const float*)d_in[0];   // [T,B,D]
    const float* z    = (const float*)d_in[1];   // [T,B,D]
    const float* h0   = (const float*)d_in[2];   // [B,D]
    const float* Wxw  = (const float*)d_in[3];   // [D,D]
    const float* Whw  = (const float*)d_in[4];   // [D,D]
    const float* bias = (const float*)d_in[5];   // [D]
    float* out = (float*)d_out;                  // [2,T,B,D]: h_all then outputs

    init_kernel<<<128, 256>>>(h0);
    gemm_wx_kernel<<<dim3(DD / 128, (TT * BB) / 128), 256>>>(x, Wxw, bias);
    scan_kernel<<<NBLK, 256>>>(z, Whw, out);
}

// round 2
// speedup vs baseline: 1.4156x; 1.4156x over previous
#include <cuda_runtime.h>
#include <math.h>

#define TT 512
#define BB 32
#define DD 1024
#define NBLK 128          // scan grid (all co-resident on 148 SMs -> barrier safe)
#define EPB 8             // e-rows of W_h per scan block
#define SCAN_THREADS 512
#define WS_STRIDE 1028    // padded W_h row stride (floats); 1028*4B = 16*257 -> 16B aligned rows

// ---------------- scratch (static device memory; no allocations) ----------------
__device__ float    g_Wx[(size_t)TT * BB * DD];   // 64 MB: precomputed x@W_x^T + b
__device__ float    g_hT[2][DD * BB];             // double-buffered h, transposed [d][b]
__device__ unsigned g_cnt[TT];                    // per-step arrival counters

// ---------------- cp.async helpers ----------------
__device__ __forceinline__ void cp16(float* dst_smem, const float* src) {
    unsigned d = (unsigned)__cvta_generic_to_shared(dst_smem);
    asm volatile("cp.async.cg.shared.global [%0], [%1], 16;" :: "r"(d), "l"(src) : "memory");
}
__device__ __forceinline__ void cp_commit() {
    asm volatile("cp.async.commit_group;" ::: "memory");
}
template <int N>
__device__ __forceinline__ void cp_wait() {
    asm volatile("cp.async.wait_group %0;" :: "n"(N) : "memory");
}

// ---------------- init: reset counters, load h0 (transposed) ----------------
__global__ void init_kernel(const float* __restrict__ h0) {
    int idx = blockIdx.x * blockDim.x + threadIdx.x;   // 0..32767
    if (idx < TT) g_cnt[idx] = 0u;
    if (idx < DD * BB) {
        int d = idx >> 5;
        int b = idx & 31;
        g_hT[0][idx] = h0[b * DD + d];   // idx == d*32 + b
    }
}

// ---------------- phase 1: Wx[m][e] = sum_k x[m][k] * W_x[e][k] + bias[e] ----------------
// M = 16384, N = 1024, K = 1024. NT gemm, 128x128 tile, BK=8, double-buffered smem,
// register prefetch of the next tile overlapped with compute.
__global__ void __launch_bounds__(256) gemm_wx_kernel(
    const float* __restrict__ x,
    const float* __restrict__ Wxw,
    const float* __restrict__ bias)
{
    __shared__ float As[2][8][128];   // [buf][k][m]
    __shared__ float Bs[2][8][128];   // [buf][k][n]

    const int tid = threadIdx.x;
    const int tx = tid & 15;
    const int ty = tid >> 4;
    const int m0 = blockIdx.y * 128;
    const int n0 = blockIdx.x * 128;

    // loader mapping: each thread fetches one float4 of A and one of B per tile
    const int lrow = tid >> 1;            // 0..127
    const int lc4  = (tid & 1) * 4;       // 0 or 4 (k offset)

    const float* pa_src = &x  [(size_t)(m0 + lrow) * DD + lc4];
    const float* pb_src = &Wxw[(size_t)(n0 + lrow) * DD + lc4];

    float acc[8][8] = {};

    // prologue: tile 0
    float4 pa = *(const float4*)pa_src;
    float4 pb = *(const float4*)pb_src;
    {
        As[0][lc4 + 0][lrow] = pa.x; As[0][lc4 + 1][lrow] = pa.y;
        As[0][lc4 + 2][lrow] = pa.z; As[0][lc4 + 3][lrow] = pa.w;
        Bs[0][lc4 + 0][lrow] = pb.x; Bs[0][lc4 + 1][lrow] = pb.y;
        Bs[0][lc4 + 2][lrow] = pb.z; Bs[0][lc4 + 3][lrow] = pb.w;
    }
    __syncthreads();

    const int NKT = DD / 8;   // 128
    for (int kt = 0; kt < NKT; kt++) {
        int cur = kt & 1;
        if (kt + 1 < NKT) {
            pa = *(const float4*)(pa_src + (size_t)(kt + 1) * 8);
            pb = *(const float4*)(pb_src + (size_t)(kt + 1) * 8);
        }

        #pragma unroll
        for (int k = 0; k < 8; k++) {
            float4 a0 = *(const float4*)&As[cur][k][ty * 8];
            float4 a1 = *(const float4*)&As[cur][k][ty * 8 + 4];
            float4 b0 = *(const float4*)&Bs[cur][k][tx * 8];
            float4 b1 = *(const float4*)&Bs[cur][k][tx * 8 + 4];
            float a[8] = {a0.x, a0.y, a0.z, a0.w, a1.x, a1.y, a1.z, a1.w};
            float b[8] = {b0.x, b0.y, b0.z, b0.w, b1.x, b1.y, b1.z, b1.w};
            #pragma unroll
            for (int i = 0; i < 8; i++)
                #pragma unroll
                for (int j = 0; j < 8; j++)
                    acc[i][j] += a[i] * b[j];
        }

        if (kt + 1 < NKT) {
            int nxt = cur ^ 1;
            As[nxt][lc4 + 0][lrow] = pa.x; As[nxt][lc4 + 1][lrow] = pa.y;
            As[nxt][lc4 + 2][lrow] = pa.z; As[nxt][lc4 + 3][lrow] = pa.w;
            Bs[nxt][lc4 + 0][lrow] = pb.x; Bs[nxt][lc4 + 1][lrow] = pb.y;
            Bs[nxt][lc4 + 2][lrow] = pb.z; Bs[nxt][lc4 + 3][lrow] = pb.w;
            __syncthreads();
        }
    }

    float4 bi0 = *(const float4*)&bias[n0 + tx * 8];
    float4 bi1 = *(const float4*)&bias[n0 + tx * 8 + 4];
    float bb[8] = {bi0.x, bi0.y, bi0.z, bi0.w, bi1.x, bi1.y, bi1.z, bi1.w};

    #pragma unroll
    for (int i = 0; i < 8; i++) {
        size_t row = (size_t)(m0 + ty * 8 + i) * DD + n0 + tx * 8;
        float4 o0 = make_float4(acc[i][0] + bb[0], acc[i][1] + bb[1],
                                acc[i][2] + bb[2], acc[i][3] + bb[3]);
        float4 o1 = make_float4(acc[i][4] + bb[4], acc[i][5] + bb[5],
                                acc[i][6] + bb[6], acc[i][7] + bb[7]);
        *(float4*)&g_Wx[row]     = o0;
        *(float4*)&g_Wx[row + 4] = o1;
    }
}

// ---------------- phase 2: persistent sequential scan ----------------
// Block bi owns e-rows [bi*8, bi*8+8) of W_h (resident in smem).
// h (128 KB, [d][b] layout) is staged into smem each step via cp.async in 4
// pipelined quarters (copy of quarter q+1 overlaps compute on quarter q).
// Thread layout: 32 d-slices x 16 spatial (2 e-groups x 8 b-groups, 4x4 tile).
__global__ void __launch_bounds__(SCAN_THREADS) scan_kernel(
    const float* __restrict__ z,
    const float* __restrict__ Wh,
    float* __restrict__ out)
{
    extern __shared__ float sm[];
    float* Ws  = sm;                        // 8 rows * WS_STRIDE
    float* hs  = sm + 8 * WS_STRIDE;        // 32768 floats, [d][b]
    float* red = hs + DD * BB;              // 16 * 257 floats

    const int tid = threadIdx.x;
    const int e0  = blockIdx.x * EPB;

    // load W_h slice (8 x 1024) into padded smem rows
    #pragma unroll
    for (int u = 0; u < 4; u++) {
        int fi = tid + u * SCAN_THREADS;    // float4 index 0..2047
        int r  = fi >> 8;                   // 0..7
        int c  = (fi & 255) * 4;            // 0..1020
        *(float4*)&Ws[r * WS_STRIDE + c] = *(const float4*)&Wh[(size_t)(e0 + r) * DD + c];
    }
    __syncthreads();

    // producer mapping
    const int ds  = tid >> 4;               // d-slice 0..31 (8 d's per quarter)
    const int sid = tid & 15;
    const int eg  = sid >> 3;               // 0..1
    const int bg  = sid & 7;                // 0..7
    const int wid = tid >> 5;
    const int lane = tid & 31;

    // consumer mapping (tid < 256): one output per thread, flat = b*8 + e
    const int cb = tid >> 3;
    const int ce = tid & 7;
    const int cslot = (tid & 255) ^ ((((tid & 255) >> 5) & 7) << 2);

    const size_t OUT2 = (size_t)TT * BB * DD;

    for (int t = 0; t < TT; t++) {
        const float* __restrict__ h = g_hT[t & 1];

        // issue all 4 quarter-copies (fire-and-forget), one commit group each
        #pragma unroll
        for (int q = 0; q < 4; q++) {
            #pragma unroll
            for (int k = 0; k < 4; k++) {
                int fi = q * 2048 + k * SCAN_THREADS + tid;   // float4 index
                cp16(&hs[fi * 4], &h[fi * 4]);
            }
            cp_commit();
        }

        // prefetch this thread's Wx and z (independent of h)
        float wx = 0.0f, zv = 0.0f;
        size_t mo = 0;
        if (tid < 256) {
            mo = (size_t)(t * BB + cb) * DD + e0 + ce;
            wx = g_Wx[mo];
            zv = z[mo];
        }

        float acc[4][4] = {};
        #pragma unroll
        for (int q = 0; q < 4; q++) {
            if (q == 0)      cp_wait<3>();
            else if (q == 1) cp_wait<2>();
            else if (q == 2) cp_wait<1>();
            else             cp_wait<0>();
            __syncthreads();

            #pragma unroll
            for (int it = 0; it < 2; it++) {
                int d = q * 256 + ds * 8 + it * 4;
                float4 h0v = *(const float4*)&hs[(d + 0) * BB + bg * 4];
                float4 h1v = *(const float4*)&hs[(d + 1) * BB + bg * 4];
                float4 h2v = *(const float4*)&hs[(d + 2) * BB + bg * 4];
                float4 h3v = *(const float4*)&hs[(d + 3) * BB + bg * 4];
                #pragma unroll
                for (int i = 0; i < 4; i++) {
                    float4 w = *(const float4*)&Ws[(eg * 4 + i) * WS_STRIDE + d];
                    acc[i][0] += w.x * h0v.x + w.y * h1v.x + w.z * h2v.x + w.w * h3v.x;
                    acc[i][1] += w.x * h0v.y + w.y * h1v.y + w.z * h2v.y + w.w * h3v.y;
                    acc[i][2] += w.x * h0v.z + w.y * h1v.z + w.z * h2v.z + w.w * h3v.z;
                    acc[i][3] += w.x * h0v.w + w.y * h1v.w + w.z * h2v.w + w.w * h3v.w;
                }
            }
        }

        // fold the two d-slices sharing each warp (lanes l and l+16)
        #pragma unroll
        for (int i = 0; i < 4; i++)
            #pragma unroll
            for (int j = 0; j < 4; j++)
                acc[i][j] += __shfl_down_sync(0xFFFFFFFFu, acc[i][j], 16);

        if (lane < 16) {
            #pragma unroll
            for (int i = 0; i < 4; i++)
                #pragma unroll
                for (int j = 0; j < 4; j++) {
                    int flat = (bg * 4 + j) * 8 + eg * 4 + i;      // b*8 + e_local
                    int slot = flat ^ (((flat >> 5) & 7) << 2);    // bank swizzle
                    red[wid * 257 + slot] = acc[i][j];
                }
        }
        __syncthreads();

        // consume: 16-way sum + epilogue
        if (tid < 256) {
            float s = 0.0f;
            #pragma unroll
            for (int r = 0; r < 16; r++) s += red[r * 257 + cslot];

            float pre = s + wx;
            float hn  = tanhf(pre);
            float sig = 1.0f / (1.0f + __expf(-zv));
            float ov  = hn * (zv * sig);

            out[mo]        = hn;   // h_all
            out[OUT2 + mo] = ov;   // outputs
            g_hT[(t + 1) & 1][(e0 + ce) * BB + cb] = hn;   // transposed next-h
            __threadfence();       // release: make h stores gpu-visible before arrive
        }
        __syncthreads();

        // inter-block barrier for step t (single arrival per block, L2 spin)
        if (tid == 0) {
            atomicAdd(&g_cnt[t], 1u);
            volatile unsigned* p = &g_cnt[t];
            while (*p < (unsigned)NBLK) { }
            __threadfence();       // acquire
        }
        __syncthreads();
    }
}

// ---------------- launch ----------------
extern "C" void kernel_launch(void* const* d_in, const int* in_sizes, int n_in,
                              void* d_out, int out_size) {
    const float* x    = (const float*)d_in[0];   // [T,B,D]
    const float* z    = (const float*)d_in[1];   // [T,B,D]
    const float* h0   = (const float*)d_in[2];   // [B,D]
    const float* Wxw  = (const float*)d_in[3];   // [D,D]
    const float* Whw  = (const float*)d_in[4];   // [D,D]
    const float* bias = (const float*)d_in[5];   // [D]
    float* out = (float*)d_out;                  // [2,T,B,D]: h_all then outputs

    const int scan_smem = (8 * WS_STRIDE + DD * BB + 16 * 257) * sizeof(float);
    cudaFuncSetAttribute(scan_kernel, cudaFuncAttributeMaxDynamicSharedMemorySize, scan_smem);

    init_kernel<<<128, 256>>>(h0);
    gemm_wx_kernel<<<dim3(DD / 128, (TT * BB) / 128), 256>>>(x, Wxw, bias);
    scan_kernel<<<NBLK, SCAN_THREADS, scan_smem>>>(z, Whw, out);
}